// round 15
// baseline (speedup 1.0000x reference)
#include <cuda_runtime.h>
#include <cuda_fp16.h>
#include <math.h>
#include <stdint.h>

// ---------------- static problem shape ----------------
#define NTOK 8192
#define DIM  1024
#define NE   7
#define CAP  2574            // int(NTOK*2/7*1.1)
#define YEXP 21              // ceil(CAP/128)
#define NT64 16              // N tiles of 64
#define NBLK_E (NE * YEXP * NT64)        // 2352 expert CTAs
#define NBLK_G (NBLK_E + 64 * NT64)      // + 1024 shared CTAs = 3376

// ---------------- scratch (device globals) ----------------
__device__ __half g_xf [NTOK * DIM];
__device__ __half g_hsf[NTOK * DIM];
__device__ __half g_hef[NE * CAP * DIM];
__device__ float  g_eout[NE * CAP * DIM];
__device__ __half g_w1t[NE * DIM * DIM];
__device__ __half g_w2t[NE * DIM * DIM];
__device__ __half g_ws1t[DIM * DIM];
__device__ __half g_ws2t[DIM * DIM];
__device__ int   g_tokE[NTOK * 2];
__device__ float g_tokG[NTOK * 2];
__device__ int   g_slotTok[NE * CAP];
__device__ float g_slotGate[NE * CAP];
__device__ int   g_tokSlot[NTOK * 2];

// ---------------- PTX helpers ----------------
__device__ __forceinline__ uint32_t smem_u32(const void* p) {
    uint32_t a;
    asm("{ .reg .u64 t; cvta.to.shared.u64 t, %1; cvt.u32.u64 %0, t; }" : "=r"(a) : "l"(p));
    return a;
}
#define SW128(x) ((x) ^ (((x) >> 3) & 0x70))
#define CP16(dst, src) asm volatile("cp.async.cg.shared.global [%0], [%1], 16;" :: "r"(dst), "l"(src))
#define CP_COMMIT() asm volatile("cp.async.commit_group;" ::: "memory")
#define CP_WAIT(n)  asm volatile("cp.async.wait_group %0;" :: "n"(n) : "memory")

#define LDSM4(R, a) \
    asm volatile("ldmatrix.sync.aligned.m8n8.x4.shared.b16 {%0,%1,%2,%3}, [%4];" \
        : "=r"((R)[0]), "=r"((R)[1]), "=r"((R)[2]), "=r"((R)[3]) : "r"(a))

#define MMA(C, A, B0, B1) \
    asm volatile("mma.sync.aligned.m16n8k16.row.col.f32.f16.f16.f32 " \
        "{%0,%1,%2,%3}, {%4,%5,%6,%7}, {%8,%9}, {%0,%1,%2,%3};" \
        : "+f"((C)[0]), "+f"((C)[1]), "+f"((C)[2]), "+f"((C)[3]) \
        : "r"((A)[0]), "r"((A)[1]), "r"((A)[2]), "r"((A)[3]), "r"(B0), "r"(B1))

// ---------------- smem: 3 stages x 24KB: A 16K | B 8K (128B rows, SW128) ----------------
#define STG_BYTES 24576u
#define NSTAGE    3
#define SMEM_BYTES (NSTAGE * 24576)
#define NCHUNK    (DIM / 64)
#define PF_DIST   2

// ---------------- merged GEMM, flat 1D grid, 128x64 CTA tile, 3 CTAs/SM ----------------
template <int PHASE>
__global__ __launch_bounds__(256, 3)
void moe_gemm(const __half* __restrict__ Ae, const __half* __restrict__ As,
              const __half* __restrict__ Be, const __half* __restrict__ Bs,
              const float* __restrict__ biasE_, const float* __restrict__ biasS_,
              __half* __restrict__ OhE, __half* __restrict__ OhS,
              float* __restrict__ OfE, float* __restrict__ OfS,
              const int* __restrict__ slotTok, const float* __restrict__ slotGate)
{
    const int bid = blockIdx.x;
    const bool sh = (bid >= NBLK_E);
    int e, yt, xt;
    if (sh) {
        int r = bid - NBLK_E;
        e = 0; yt = r >> 4; xt = r & 15;
    } else {
        e = bid / (YEXP * NT64);
        int r = bid % (YEXP * NT64);
        yt = r >> 4; xt = r & 15;
    }
    const int m0 = yt * 128;
    const int n0 = xt * 64;

    if (!sh && __ldg(&slotTok[e * CAP + m0]) >= NTOK) return;

    extern __shared__ char smem[];
    const int tid  = threadIdx.x;
    const int wid  = tid >> 5;
    const int lane = tid & 31;
    const uint32_t sb = smem_u32(smem);

    const float* bias = sh ? biasS_ : (biasE_ + e * DIM);
    const __half* Bt  = sh ? Bs : (Be + ((size_t)e << 20));

    // ---- per-thread source rows for fill ----
    const __half* src;
    uint32_t fillDst;      // smem offset within stage (pre-swizzled row base)
    int nCp;               // CP16s per thread
    int srcStep;           // halfs into row per chunk offset base
    if (tid < 128) {
        const int rA = tid;
        if (sh) {
            src = As + (size_t)(m0 + rA) * DIM;
        } else if (PHASE == 1) {
            int slot = m0 + rA;
            int tok  = (slot < CAP) ? __ldg(&slotTok[e * CAP + slot]) : NTOK;
            if (tok >= NTOK) tok = 0;
            src = Ae + (size_t)tok * DIM;
        } else {
            int r = m0 + rA; if (r > CAP - 1) r = CAP - 1;
            src = Ae + ((size_t)e * CAP + r) * DIM;
        }
        fillDst = (uint32_t)rA * 128u;
        nCp = 8; srcStep = 0;
    } else {
        const int t  = tid - 128;
        const int rB = t >> 1;
        const int h2 = t & 1;
        src = Bt + (size_t)(n0 + rB) * DIM;
        fillDst = 16384u + (uint32_t)rB * 128u + (uint32_t)h2 * 64u;
        nCp = 4; srcStep = h2 * 32;
    }

    auto fill = [&](int c) {
        uint32_t stg = sb + (uint32_t)(c % NSTAGE) * STG_BYTES;
        const __half* s = src + c * 64 + srcStep;
        if (nCp == 8) {
#pragma unroll
            for (int q = 0; q < 8; q++)
                CP16(stg + SW128(fillDst + q * 16u), s + q * 8);
        } else {
#pragma unroll
            for (int q = 0; q < 4; q++)
                CP16(stg + SW128(fillDst + q * 16u), s + q * 8);
        }
        CP_COMMIT();
    };

    // ---- warp tiling: 4 (m) x 2 (n); warp tile 32x32 ----
    const int wm = (wid & 3) * 32;
    const int wn = (wid >> 2) * 32;

    const uint32_t aRowL = (uint32_t)(wm + ((lane >> 3) & 1) * 8 + (lane & 7));
    const uint32_t aOffL = (uint32_t)((lane >> 4) * 16);
    const uint32_t bRowL = (uint32_t)(wn + ((lane >> 4) & 1) * 8 + (lane & 7));
    const uint32_t bOffL = (uint32_t)(((lane >> 3) & 1) * 16);

    float acc[2][4][4];
#pragma unroll
    for (int i = 0; i < 2; i++)
#pragma unroll
        for (int j = 0; j < 4; j++)
#pragma unroll
            for (int q = 0; q < 4; q++) acc[i][j][q] = 0.f;

    fill(0); fill(1);
#pragma unroll 1
    for (int c = 0; c < NCHUNK; c++) {
        if (c < NCHUNK - 1) { CP_WAIT(1); } else { CP_WAIT(0); }
        __syncthreads();
        if (c + PF_DIST < NCHUNK) fill(c + PF_DIST);

        uint32_t stg  = sb + (uint32_t)(c % NSTAGE) * STG_BYTES;
        uint32_t stgB = stg + 16384u;

#pragma unroll
        for (int ks = 0; ks < 4; ks++) {
            uint32_t bf[4][2];
#pragma unroll
            for (int bt = 0; bt < 2; bt++) {
                uint32_t r4[4];
                LDSM4(r4, stgB + SW128((bRowL + bt * 16u) * 128u + bOffL + ks * 32u));
                bf[bt * 2][0] = r4[0]; bf[bt * 2][1] = r4[1];
                bf[bt * 2 + 1][0] = r4[2]; bf[bt * 2 + 1][1] = r4[3];
            }
#pragma unroll
            for (int mt = 0; mt < 2; mt++) {
                uint32_t a4[4];
                LDSM4(a4, stg + SW128((aRowL + mt * 16u) * 128u + aOffL + ks * 32u));
#pragma unroll
                for (int nt = 0; nt < 4; nt++)
                    MMA(acc[mt][nt], a4, bf[nt][0], bf[nt][1]);
            }
        }
    }

    // ---- epilogue ----
#pragma unroll
    for (int mt = 0; mt < 2; mt++) {
#pragma unroll
        for (int h = 0; h < 2; h++) {
            int rloc = wm + mt * 16 + (lane >> 2) + h * 8;
            int grow = m0 + rloc;

            bool   valid = true;
            size_t obase = 0;
            float  gate  = 0.f;
            if (sh) {
                obase = (size_t)grow * DIM;
            } else if (PHASE == 1) {
                valid = (grow < CAP);
                obase = ((size_t)e * CAP + (valid ? grow : 0)) * DIM;
            } else {
                valid = false;
                if (grow < CAP) {
                    int tok = __ldg(&slotTok[e * CAP + grow]);
                    if (tok < NTOK) {
                        gate  = __ldg(&slotGate[e * CAP + grow]);
                        obase = ((size_t)e * CAP + grow) * DIM;
                        valid = true;
                    }
                }
            }
            if (!valid) continue;

#pragma unroll
            for (int nt = 0; nt < 4; nt++) {
                int nc = n0 + wn + nt * 8 + (lane & 3) * 2;
                float v0 = acc[mt][nt][h * 2 + 0] + __ldg(&bias[nc]);
                float v1 = acc[mt][nt][h * 2 + 1] + __ldg(&bias[nc + 1]);
                if (PHASE == 1) {
                    v0 = fmaxf(v0, 0.f); v1 = fmaxf(v1, 0.f);
                    __half h0 = __float2half_rn(v0);
                    __half h1 = __float2half_rn(v1);
                    uint32_t hp = (uint32_t)*(ushort*)&h0 | ((uint32_t)*(ushort*)&h1 << 16);
                    __half* O = sh ? OhS : OhE;
                    *reinterpret_cast<uint32_t*>(O + obase + nc) = hp;
                } else if (sh) {
                    *reinterpret_cast<float2*>(OfS + obase + nc) = make_float2(v0, v1);
                } else {
                    *reinterpret_cast<float2*>(OfE + obase + nc) =
                        make_float2(gate * v0, gate * v1);
                }
            }
        }
    }
}

// ---------------- prep: transpose + fp16 weights (experts z<NE, shared z==NE) ----------------
__global__ void prep_w_k(const float* __restrict__ We, const float* __restrict__ Ws,
                         __half* __restrict__ Te, __half* __restrict__ Ts)
{
    __shared__ float tile[32][33];
    const int z = blockIdx.z;
    const bool sh = (z == NE);
    const size_t mo = sh ? 0 : ((size_t)z << 20);
    const float* Wm = (sh ? Ws : We) + mo;
    __half*      Tm = (sh ? Ts : Te) + mo;
    int n0 = blockIdx.x * 32, k0 = blockIdx.y * 32;
    for (int r = threadIdx.y; r < 32; r += 8)
        tile[r][threadIdx.x] = Wm[(size_t)(k0 + r) * DIM + n0 + threadIdx.x];
    __syncthreads();
    for (int r = threadIdx.y; r < 32; r += 8) {
        float v = tile[threadIdx.x][r];
        Tm[(size_t)(n0 + r) * DIM + k0 + threadIdx.x] = __float2half_rn(v);
    }
}

// ---------------- router (also produces fp16 x) ----------------
__global__ void router_k(const float* __restrict__ x, const float* __restrict__ noise,
                         const float* __restrict__ Wr, const float* __restrict__ br,
                         const float* __restrict__ Wn, const float* __restrict__ bn,
                         int* __restrict__ tokE, float* __restrict__ tokG,
                         __half* __restrict__ xf)
{
    int gw   = (blockIdx.x * blockDim.x + threadIdx.x) >> 5;
    int lane = threadIdx.x & 31;
    if (gw >= NTOK) return;
    const float* xr = x + (size_t)gw * DIM;
    __half*      xo = xf + (size_t)gw * DIM;
    float aR[NE], aN[NE];
#pragma unroll
    for (int e = 0; e < NE; e++) { aR[e] = 0.f; aN[e] = 0.f; }
    for (int kk = 0; kk < DIM / 32; ++kk) {
        int   k  = kk * 32 + lane;
        float xv = xr[k];
        xo[k] = __float2half_rn(xv);
        const float* wr = Wr + (size_t)k * NE;
        const float* wn = Wn + (size_t)k * NE;
#pragma unroll
        for (int e = 0; e < NE; e++) {
            aR[e] = fmaf(xv, __ldg(wr + e), aR[e]);
            aN[e] = fmaf(xv, __ldg(wn + e), aN[e]);
        }
    }
#pragma unroll
    for (int off = 16; off; off >>= 1) {
#pragma unroll
        for (int e = 0; e < NE; e++) {
            aR[e] += __shfl_xor_sync(0xffffffffu, aR[e], off);
            aN[e] += __shfl_xor_sync(0xffffffffu, aN[e], off);
        }
    }
    if (lane == 0) {
        float v1 = -1e30f, v2 = -1e30f; int i1 = 0, i2 = 0;
#pragma unroll
        for (int e = 0; e < NE; e++) {
            float ln = aN[e] + bn[e];
            float sp = fmaxf(ln, 0.f) + log1pf(expf(-fabsf(ln)));
            float v  = aR[e] + br[e] + noise[(size_t)gw * NE + e] * sp;
            if (v > v1)      { v2 = v1; i2 = i1; v1 = v; i1 = e; }
            else if (v > v2) { v2 = v;  i2 = e; }
        }
        float d = expf(v2 - v1);
        float inv = 1.f / (1.f + d);
        tokE[2 * gw] = i1; tokE[2 * gw + 1] = i2;
        tokG[2 * gw] = inv; tokG[2 * gw + 1] = d * inv;
    }
}

// ---------------- load-balance loss ----------------
__global__ void lbl_k(const int* __restrict__ tokE, const float* __restrict__ tokG,
                      float* __restrict__ out, int writeLbl)
{
    __shared__ float ws[32][2 * NE];
    int tid = threadIdx.x, lane = tid & 31, wid = tid >> 5;
    float pg[NE], pc[NE];
#pragma unroll
    for (int e = 0; e < NE; e++) { pg[e] = 0.f; pc[e] = 0.f; }
    for (int t = tid; t < NTOK; t += 1024) {
        int   e0 = tokE[2 * t], e1 = tokE[2 * t + 1];
        float g0 = tokG[2 * t], g1 = tokG[2 * t + 1];
#pragma unroll
        for (int e = 0; e < NE; e++) {
            pg[e] += (e0 == e ? g0 : 0.f) + (e1 == e ? g1 : 0.f);
            pc[e] += (e0 == e ? 1.f : 0.f) + (e1 == e ? 1.f : 0.f);
        }
    }
#pragma unroll
    for (int off = 16; off; off >>= 1) {
#pragma unroll
        for (int e = 0; e < NE; e++) {
            pg[e] += __shfl_xor_sync(0xffffffffu, pg[e], off);
            pc[e] += __shfl_xor_sync(0xffffffffu, pc[e], off);
        }
    }
    if (lane == 0) {
#pragma unroll
        for (int e = 0; e < NE; e++) { ws[wid][e] = pg[e]; ws[wid][NE + e] = pc[e]; }
    }
    __syncthreads();
    if (tid == 0 && writeLbl) {
        float sums[2 * NE];
#pragma unroll
        for (int j = 0; j < 2 * NE; j++) {
            float s = 0.f;
            for (int w = 0; w < 32; w++) s += ws[w][j];
            sums[j] = s;
        }
        float l = 0.f;
        for (int e = 0; e < NE; e++)
            l += (sums[e] / (float)NTOK) * (sums[NE + e] / (float)NTOK);
        out[(size_t)NTOK * DIM] = l * (float)NE;
    }
}

// ---------------- capacity dispatch ----------------
__global__ void scan_k(const int* __restrict__ tokE, const float* __restrict__ tokG,
                       int* __restrict__ slotTok, float* __restrict__ slotGate,
                       int* __restrict__ tokSlot)
{
    const int e = blockIdx.x, tid = threadIdx.x;
    const int lane = tid & 31, wid = tid >> 5;
    __shared__ int wsum[32];
    __shared__ int wbase[32];
    __shared__ int blksum;

    for (int c = tid; c < CAP; c += 1024) {
        slotTok[e * CAP + c]  = NTOK;
        slotGate[e * CAP + c] = 0.f;
    }
    __syncthreads();

    int base = 0;
    for (int tile = 0; tile < NTOK; tile += 1024) {
        int t  = tile + tid;
        int e0 = tokE[2 * t], e1 = tokE[2 * t + 1];
        int flag = (e0 == e) || (e1 == e);
        uint32_t b = __ballot_sync(0xffffffffu, flag);
        int lpre = __popc(b & ((1u << lane) - 1));
        if (lane == 0) wsum[wid] = __popc(b);
        __syncthreads();
        if (wid == 0) {
            int v = wsum[lane];
            int inc = v;
#pragma unroll
            for (int off = 1; off < 32; off <<= 1) {
                int y = __shfl_up_sync(0xffffffffu, inc, off);
                if (lane >= off) inc += y;
            }
            wbase[lane] = inc - v;
            if (lane == 31) blksum = inc;
        }
        __syncthreads();
        int pos = base + wbase[wid] + lpre;
        if (flag) {
            int k = (e0 == e) ? 0 : 1;
            if (pos < CAP) {
                slotTok[e * CAP + pos]  = t;
                slotGate[e * CAP + pos] = (e0 == e) ? tokG[2 * t] : tokG[2 * t + 1];
                tokSlot[2 * t + k] = e * CAP + pos;
            } else {
                tokSlot[2 * t + k] = -1;
            }
        }
        base += blksum;
        __syncthreads();
    }
}

// ---------------- combine ----------------
__global__ void combine_k(const int* __restrict__ tokSlot,
                          const float* __restrict__ eout, float* __restrict__ out)
{
    int t = blockIdx.x;
    int d = threadIdx.x * 4;
    int s0 = __ldg(&tokSlot[2 * t]);
    int s1 = __ldg(&tokSlot[2 * t + 1]);
    float4 v = *reinterpret_cast<float4*>(out + (size_t)t * DIM + d);
    if (s0 >= 0) {
        float4 a = *reinterpret_cast<const float4*>(eout + (size_t)s0 * DIM + d);
        v.x += a.x; v.y += a.y; v.z += a.z; v.w += a.w;
    }
    if (s1 >= 0) {
        float4 a = *reinterpret_cast<const float4*>(eout + (size_t)s1 * DIM + d);
        v.x += a.x; v.y += a.y; v.z += a.z; v.w += a.w;
    }
    *reinterpret_cast<float4*>(out + (size_t)t * DIM + d) = v;
}

// ---------------- host ----------------
extern "C" void kernel_launch(void* const* d_in, const int* in_sizes, int n_in,
                              void* d_out, int out_size)
{
    const float* x   = (const float*)d_in[0];
    const float* noi = (const float*)d_in[1];
    const float* Wr  = (const float*)d_in[2];
    const float* br  = (const float*)d_in[3];
    const float* Wn  = (const float*)d_in[4];
    const float* bn  = (const float*)d_in[5];
    const float* W1  = (const float*)d_in[6];
    const float* b1  = (const float*)d_in[7];
    const float* W2  = (const float*)d_in[8];
    const float* b2  = (const float*)d_in[9];
    const float* Ws1 = (const float*)d_in[10];
    const float* bs1 = (const float*)d_in[11];
    const float* Ws2 = (const float*)d_in[12];
    const float* bs2 = (const float*)d_in[13];
    float* out = (float*)d_out;

    __half *xf, *hsf, *hef, *w1t, *w2t, *ws1t, *ws2t;
    float *eout;
    int *tokE, *slotTok, *tokSlot; float *tokG, *slotGate;
    cudaGetSymbolAddress((void**)&xf, g_xf);
    cudaGetSymbolAddress((void**)&hsf, g_hsf);
    cudaGetSymbolAddress((void**)&hef, g_hef);
    cudaGetSymbolAddress((void**)&eout, g_eout);
    cudaGetSymbolAddress((void**)&w1t, g_w1t);
    cudaGetSymbolAddress((void**)&w2t, g_w2t);
    cudaGetSymbolAddress((void**)&ws1t, g_ws1t);
    cudaGetSymbolAddress((void**)&ws2t, g_ws2t);
    cudaGetSymbolAddress((void**)&tokE, g_tokE); cudaGetSymbolAddress((void**)&tokG, g_tokG);
    cudaGetSymbolAddress((void**)&slotTok, g_slotTok); cudaGetSymbolAddress((void**)&slotGate, g_slotGate);
    cudaGetSymbolAddress((void**)&tokSlot, g_tokSlot);

    cudaFuncSetAttribute(moe_gemm<1>, cudaFuncAttributeMaxDynamicSharedMemorySize, SMEM_BYTES);
    cudaFuncSetAttribute(moe_gemm<2>, cudaFuncAttributeMaxDynamicSharedMemorySize, SMEM_BYTES);

    dim3 tb(32, 8);
    dim3 gW(32, 32, NE + 1);

    router_k<<<1024, 256>>>(x, noi, Wr, br, Wn, bn, tokE, tokG, xf);        // 0
    prep_w_k<<<gW, tb>>>(W1, Ws1, w1t, ws1t);                               // 1
    scan_k<<<NE, 1024>>>(tokE, tokG, slotTok, slotGate, tokSlot);           // 2

    // 3: merged GEMM phase 1  (ncu-profiled launch)
    moe_gemm<1><<<NBLK_G, 256, SMEM_BYTES>>>(xf, xf, w1t, ws1t, b1, bs1,
                                             hef, hsf, nullptr, nullptr,
                                             slotTok, slotGate);

    lbl_k<<<1, 1024>>>(tokE, tokG, out, (out_size > NTOK * DIM) ? 1 : 0);   // 4
    prep_w_k<<<gW, tb>>>(W2, Ws2, w2t, ws2t);                               // 5

    // 6: merged GEMM phase 2
    moe_gemm<2><<<NBLK_G, 256, SMEM_BYTES>>>(hef, hsf, w2t, ws2t, b2, bs2,
                                             nullptr, nullptr, eout, out,
                                             slotTok, slotGate);

    combine_k<<<NTOK, 256>>>(tokSlot, eout, out);                           // 7
    (void)in_sizes; (void)n_in;
}

// round 17
// speedup vs baseline: 1.0435x; 1.0435x over previous
#include <cuda_runtime.h>
#include <cuda_fp16.h>
#include <math.h>
#include <stdint.h>

// ---------------- static problem shape ----------------
#define NTOK 8192
#define DIM  1024
#define NE   7
#define CAP  2574            // int(NTOK*2/7*1.1)
#define YEXP 21              // ceil(CAP/128)
#define NBLK_E (NE * YEXP * 8)      // 1176 expert CTAs
#define NBLK_G (NBLK_E + 64 * 8)    // + 512 shared CTAs = 1688

// ---------------- scratch (device globals) ----------------
__device__ __half g_xf [NTOK * DIM];
__device__ __half g_hsf[NTOK * DIM];
__device__ __half g_hef[NE * CAP * DIM];
__device__ float  g_eout[NE * CAP * DIM];
__device__ __half g_w1t[NE * DIM * DIM];
__device__ __half g_w2t[NE * DIM * DIM];
__device__ __half g_ws1t[DIM * DIM];
__device__ __half g_ws2t[DIM * DIM];
__device__ int   g_tokE[NTOK * 2];
__device__ float g_tokG[NTOK * 2];
__device__ int   g_slotTok[NE * CAP];
__device__ float g_slotGate[NE * CAP];
__device__ int   g_tokSlot[NTOK * 2];

// ---------------- PTX helpers ----------------
__device__ __forceinline__ uint32_t smem_u32(const void* p) {
    uint32_t a;
    asm("{ .reg .u64 t; cvta.to.shared.u64 t, %1; cvt.u32.u64 %0, t; }" : "=r"(a) : "l"(p));
    return a;
}
#define SW128(x) ((x) ^ (((x) >> 3) & 0x70))
#define CP16(dst, src) asm volatile("cp.async.cg.shared.global [%0], [%1], 16;" :: "r"(dst), "l"(src))
#define CP_COMMIT() asm volatile("cp.async.commit_group;" ::: "memory")
#define CP_WAIT(n)  asm volatile("cp.async.wait_group %0;" :: "n"(n) : "memory")

#define LDSM4(R, a) \
    asm volatile("ldmatrix.sync.aligned.m8n8.x4.shared.b16 {%0,%1,%2,%3}, [%4];" \
        : "=r"((R)[0]), "=r"((R)[1]), "=r"((R)[2]), "=r"((R)[3]) : "r"(a))

#define MMA(C, A, B0, B1) \
    asm volatile("mma.sync.aligned.m16n8k16.row.col.f32.f16.f16.f32 " \
        "{%0,%1,%2,%3}, {%4,%5,%6,%7}, {%8,%9}, {%0,%1,%2,%3};" \
        : "+f"((C)[0]), "+f"((C)[1]), "+f"((C)[2]), "+f"((C)[3]) \
        : "r"((A)[0]), "r"((A)[1]), "r"((A)[2]), "r"((A)[3]), "r"(B0), "r"(B1))

// ---------------- smem: 3 stages x 32KB: A 16K | B 16K (128B rows, SW128) ----------------
#define STG_BYTES 32768u
#define NSTAGE    3
#define SMEM_BYTES (NSTAGE * 32768)
#define NCHUNK    (DIM / 64)
#define PF_DIST   2

// ---------------- merged GEMM, flat 1D grid (R14 config: best measured) ----------------
template <int PHASE>
__global__ __launch_bounds__(256, 2)
void moe_gemm(const __half* __restrict__ Ae, const __half* __restrict__ As,
              const __half* __restrict__ Be, const __half* __restrict__ Bs,
              const float* __restrict__ biasE_, const float* __restrict__ biasS_,
              __half* __restrict__ OhE, __half* __restrict__ OhS,
              float* __restrict__ OfE, float* __restrict__ OfS,
              const int* __restrict__ slotTok, const float* __restrict__ slotGate)
{
    const int bid = blockIdx.x;
    const bool sh = (bid >= NBLK_E);
    int e, yt, xt;
    if (sh) {
        int r = bid - NBLK_E;
        e = 0; yt = r >> 3; xt = r & 7;
    } else {
        e = bid / (YEXP * 8);
        int r = bid % (YEXP * 8);
        yt = r >> 3; xt = r & 7;
    }
    const int m0 = yt * 128;
    const int n0 = xt * 128;

    if (!sh && __ldg(&slotTok[e * CAP + m0]) >= NTOK) return;

    extern __shared__ char smem[];
    const int tid  = threadIdx.x;
    const int wid  = tid >> 5;
    const int lane = tid & 31;
    const uint32_t sb = smem_u32(smem);

    const float* bias = sh ? biasS_ : (biasE_ + e * DIM);
    const __half* Bt  = sh ? Bs : (Be + ((size_t)e << 20));

    const int rA = tid & 127;
    const __half* src;
    if (tid < 128) {
        if (sh) {
            src = As + (size_t)(m0 + rA) * DIM;
        } else if (PHASE == 1) {
            int slot = m0 + rA;
            int tok  = (slot < CAP) ? __ldg(&slotTok[e * CAP + slot]) : NTOK;
            if (tok >= NTOK) tok = 0;
            src = Ae + (size_t)tok * DIM;
        } else {
            int r = m0 + rA; if (r > CAP - 1) r = CAP - 1;
            src = Ae + ((size_t)e * CAP + r) * DIM;
        }
    } else {
        src = Bt + (size_t)(n0 + rA) * DIM;
    }
    const uint32_t dstBase = (tid < 128) ? 0u : 16384u;
    const uint32_t rowOff  = (uint32_t)rA * 128u;

    auto fill = [&](int c) {
        uint32_t stg = sb + (uint32_t)(c % NSTAGE) * STG_BYTES + dstBase;
        const __half* s = src + c * 64;
#pragma unroll
        for (int q = 0; q < 8; q++)
            CP16(stg + SW128(rowOff + q * 16u), s + q * 8);
        CP_COMMIT();
    };

    const int wm = (wid & 1) * 64;
    const int wn = (wid >> 1) * 32;

    const uint32_t aRowL = (uint32_t)(wm + ((lane >> 3) & 1) * 8 + (lane & 7));
    const uint32_t aOffL = (uint32_t)((lane >> 4) * 16);
    const uint32_t bRowL = (uint32_t)(wn + ((lane >> 4) & 1) * 8 + (lane & 7));
    const uint32_t bOffL = (uint32_t)(((lane >> 3) & 1) * 16);

    float acc[4][4][4];
#pragma unroll
    for (int i = 0; i < 4; i++)
#pragma unroll
        for (int j = 0; j < 4; j++)
#pragma unroll
            for (int q = 0; q < 4; q++) acc[i][j][q] = 0.f;

    fill(0); fill(1);
#pragma unroll 1
    for (int c = 0; c < NCHUNK; c++) {
        if (c < NCHUNK - 1) { CP_WAIT(1); } else { CP_WAIT(0); }
        __syncthreads();
        if (c + PF_DIST < NCHUNK) fill(c + PF_DIST);

        uint32_t stg  = sb + (uint32_t)(c % NSTAGE) * STG_BYTES;
        uint32_t stgB = stg + 16384u;

        uint32_t bf[2][4][2];
        uint32_t areg[3][4];

#pragma unroll
        for (int bt = 0; bt < 2; bt++) {
            uint32_t r4[4];
            LDSM4(r4, stgB + SW128((bRowL + bt * 16u) * 128u + bOffL));
            bf[0][bt * 2][0] = r4[0]; bf[0][bt * 2][1] = r4[1];
            bf[0][bt * 2 + 1][0] = r4[2]; bf[0][bt * 2 + 1][1] = r4[3];
        }
        LDSM4(areg[0], stg + SW128(aRowL * 128u + aOffL));
        LDSM4(areg[1], stg + SW128((aRowL + 16u) * 128u + aOffL));

#pragma unroll
        for (int ks = 0; ks < 4; ks++) {
            const int bcur = ks & 1, bnxt = bcur ^ 1;
#pragma unroll
            for (int mt = 0; mt < 4; mt++) {
                const int slot = ks * 4 + mt;
                const int ap = slot % 3;
                if (mt == 0 && ks < 3) {
#pragma unroll
                    for (int bt = 0; bt < 2; bt++) {
                        uint32_t r4[4];
                        LDSM4(r4, stgB +
                              SW128((bRowL + bt * 16u) * 128u + bOffL + (ks + 1) * 32u));
                        bf[bnxt][bt * 2][0] = r4[0]; bf[bnxt][bt * 2][1] = r4[1];
                        bf[bnxt][bt * 2 + 1][0] = r4[2]; bf[bnxt][bt * 2 + 1][1] = r4[3];
                    }
                }
                {
                    const int ns = slot + 2;
                    if (ns < 16) {
                        const int nk = ns >> 2, nm = ns & 3;
                        LDSM4(areg[ns % 3],
                              stg + SW128((aRowL + nm * 16u) * 128u + aOffL + nk * 32u));
                    }
                }
#pragma unroll
                for (int nt = 0; nt < 4; nt++)
                    MMA(acc[mt][nt], areg[ap], bf[bcur][nt][0], bf[bcur][nt][1]);
            }
        }
    }

    // ---- epilogue ----
#pragma unroll
    for (int mt = 0; mt < 4; mt++) {
#pragma unroll
        for (int h = 0; h < 2; h++) {
            int rloc = wm + mt * 16 + (lane >> 2) + h * 8;
            int grow = m0 + rloc;

            bool   valid = true;
            size_t obase = 0;
            float  gate  = 0.f;
            if (sh) {
                obase = (size_t)grow * DIM;
            } else if (PHASE == 1) {
                valid = (grow < CAP);
                obase = ((size_t)e * CAP + (valid ? grow : 0)) * DIM;
            } else {
                valid = false;
                if (grow < CAP) {
                    int tok = __ldg(&slotTok[e * CAP + grow]);
                    if (tok < NTOK) {
                        gate  = __ldg(&slotGate[e * CAP + grow]);
                        obase = ((size_t)e * CAP + grow) * DIM;
                        valid = true;
                    }
                }
            }
            if (!valid) continue;

#pragma unroll
            for (int nt = 0; nt < 4; nt++) {
                int nc = n0 + wn + nt * 8 + (lane & 3) * 2;
                float v0 = acc[mt][nt][h * 2 + 0] + __ldg(&bias[nc]);
                float v1 = acc[mt][nt][h * 2 + 1] + __ldg(&bias[nc + 1]);
                if (PHASE == 1) {
                    v0 = fmaxf(v0, 0.f); v1 = fmaxf(v1, 0.f);
                    __half h0 = __float2half_rn(v0);
                    __half h1 = __float2half_rn(v1);
                    uint32_t hp = (uint32_t)*(ushort*)&h0 | ((uint32_t)*(ushort*)&h1 << 16);
                    __half* O = sh ? OhS : OhE;
                    *reinterpret_cast<uint32_t*>(O + obase + nc) = hp;
                } else if (sh) {
                    *reinterpret_cast<float2*>(OfS + obase + nc) = make_float2(v0, v1);
                } else {
                    *reinterpret_cast<float2*>(OfE + obase + nc) =
                        make_float2(gate * v0, gate * v1);
                }
            }
        }
    }
}

// ---------------- prep: transpose + fp16 ALL weights in one launch ----------------
// z: 0..6 -> W1 experts, 7 -> Ws1, 8..14 -> W2 experts, 15 -> Ws2
__global__ void prep_w_all_k(const float* __restrict__ W1, const float* __restrict__ Ws1,
                             const float* __restrict__ W2, const float* __restrict__ Ws2,
                             __half* __restrict__ T1, __half* __restrict__ Ts1,
                             __half* __restrict__ T2, __half* __restrict__ Ts2)
{
    __shared__ float tile[32][33];
    const int z = blockIdx.z;
    const float* Wm;
    __half* Tm;
    if (z < NE)            { Wm = W1  + ((size_t)z << 20);        Tm = T1  + ((size_t)z << 20); }
    else if (z == NE)      { Wm = Ws1;                            Tm = Ts1; }
    else if (z < 2*NE + 1) { Wm = W2  + ((size_t)(z - NE - 1) << 20); Tm = T2 + ((size_t)(z - NE - 1) << 20); }
    else                   { Wm = Ws2;                            Tm = Ts2; }

    int n0 = blockIdx.x * 32, k0 = blockIdx.y * 32;
    for (int r = threadIdx.y; r < 32; r += 8)
        tile[r][threadIdx.x] = Wm[(size_t)(k0 + r) * DIM + n0 + threadIdx.x];
    __syncthreads();
    for (int r = threadIdx.y; r < 32; r += 8) {
        float v = tile[threadIdx.x][r];
        Tm[(size_t)(n0 + r) * DIM + k0 + threadIdx.x] = __float2half_rn(v);
    }
}

// ---------------- router (also produces fp16 x; zeroes lbl slot) ----------------
__global__ void router_k(const float* __restrict__ x, const float* __restrict__ noise,
                         const float* __restrict__ Wr, const float* __restrict__ br,
                         const float* __restrict__ Wn, const float* __restrict__ bn,
                         int* __restrict__ tokE, float* __restrict__ tokG,
                         __half* __restrict__ xf, float* __restrict__ out, int writeLbl)
{
    int gw   = (blockIdx.x * blockDim.x + threadIdx.x) >> 5;
    int lane = threadIdx.x & 31;
    if (gw >= NTOK) return;
    if (gw == 0 && lane == 0 && writeLbl) out[(size_t)NTOK * DIM] = 0.f;
    const float* xr = x + (size_t)gw * DIM;
    __half*      xo = xf + (size_t)gw * DIM;
    float aR[NE], aN[NE];
#pragma unroll
    for (int e = 0; e < NE; e++) { aR[e] = 0.f; aN[e] = 0.f; }
    for (int kk = 0; kk < DIM / 32; ++kk) {
        int   k  = kk * 32 + lane;
        float xv = xr[k];
        xo[k] = __float2half_rn(xv);
        const float* wr = Wr + (size_t)k * NE;
        const float* wn = Wn + (size_t)k * NE;
#pragma unroll
        for (int e = 0; e < NE; e++) {
            aR[e] = fmaf(xv, __ldg(wr + e), aR[e]);
            aN[e] = fmaf(xv, __ldg(wn + e), aN[e]);
        }
    }
#pragma unroll
    for (int off = 16; off; off >>= 1) {
#pragma unroll
        for (int e = 0; e < NE; e++) {
            aR[e] += __shfl_xor_sync(0xffffffffu, aR[e], off);
            aN[e] += __shfl_xor_sync(0xffffffffu, aN[e], off);
        }
    }
    if (lane == 0) {
        float v1 = -1e30f, v2 = -1e30f; int i1 = 0, i2 = 0;
#pragma unroll
        for (int e = 0; e < NE; e++) {
            float ln = aN[e] + bn[e];
            float sp = fmaxf(ln, 0.f) + log1pf(expf(-fabsf(ln)));
            float v  = aR[e] + br[e] + noise[(size_t)gw * NE + e] * sp;
            if (v > v1)      { v2 = v1; i2 = i1; v1 = v; i1 = e; }
            else if (v > v2) { v2 = v;  i2 = e; }
        }
        float d = expf(v2 - v1);
        float inv = 1.f / (1.f + d);
        tokE[2 * gw] = i1; tokE[2 * gw + 1] = i2;
        tokG[2 * gw] = inv; tokG[2 * gw + 1] = d * inv;
    }
}

// ---------------- capacity dispatch + fused lbl ----------------
__global__ void scan_k(const int* __restrict__ tokE, const float* __restrict__ tokG,
                       int* __restrict__ slotTok, float* __restrict__ slotGate,
                       int* __restrict__ tokSlot, float* __restrict__ out, int writeLbl)
{
    const int e = blockIdx.x, tid = threadIdx.x;
    const int lane = tid & 31, wid = tid >> 5;
    __shared__ int wsum[32];
    __shared__ int wbase[32];
    __shared__ int blksum;
    __shared__ float gsh[32];

    for (int c = tid; c < CAP; c += 1024) {
        slotTok[e * CAP + c]  = NTOK;
        slotGate[e * CAP + c] = 0.f;
    }
    __syncthreads();

    int base = 0;
    float gacc = 0.f;
    for (int tile = 0; tile < NTOK; tile += 1024) {
        int t  = tile + tid;
        int e0 = tokE[2 * t], e1 = tokE[2 * t + 1];
        int flag = (e0 == e) || (e1 == e);
        float gv = (e0 == e) ? tokG[2 * t] : ((e1 == e) ? tokG[2 * t + 1] : 0.f);
        gacc += gv;
        uint32_t b = __ballot_sync(0xffffffffu, flag);
        int lpre = __popc(b & ((1u << lane) - 1));
        if (lane == 0) wsum[wid] = __popc(b);
        __syncthreads();
        if (wid == 0) {
            int v = wsum[lane];
            int inc = v;
#pragma unroll
            for (int off = 1; off < 32; off <<= 1) {
                int y = __shfl_up_sync(0xffffffffu, inc, off);
                if (lane >= off) inc += y;
            }
            wbase[lane] = inc - v;
            if (lane == 31) blksum = inc;
        }
        __syncthreads();
        int pos = base + wbase[wid] + lpre;
        if (flag) {
            int k = (e0 == e) ? 0 : 1;
            if (pos < CAP) {
                slotTok[e * CAP + pos]  = t;
                slotGate[e * CAP + pos] = gv;
                tokSlot[2 * t + k] = e * CAP + pos;
            } else {
                tokSlot[2 * t + k] = -1;
            }
        }
        base += blksum;
        __syncthreads();
    }

    // fused lbl: term_e = NE * (gsum/NTOK) * (count/NTOK); count = base (pre-clip)
    if (writeLbl) {
#pragma unroll
        for (int off = 16; off; off >>= 1)
            gacc += __shfl_xor_sync(0xffffffffu, gacc, off);
        if (lane == 0) gsh[wid] = gacc;
        __syncthreads();
        if (tid == 0) {
            float gsum = 0.f;
            for (int w = 0; w < 32; w++) gsum += gsh[w];
            float term = (float)NE * (gsum / (float)NTOK) * ((float)base / (float)NTOK);
            atomicAdd(out + (size_t)NTOK * DIM, term);
        }
    }
}

// ---------------- combine ----------------
__global__ void combine_k(const int* __restrict__ tokSlot,
                          const float* __restrict__ eout, float* __restrict__ out)
{
    int t = blockIdx.x;
    int d = threadIdx.x * 4;
    int s0 = __ldg(&tokSlot[2 * t]);
    int s1 = __ldg(&tokSlot[2 * t + 1]);
    float4 v = *reinterpret_cast<float4*>(out + (size_t)t * DIM + d);
    if (s0 >= 0) {
        float4 a = *reinterpret_cast<const float4*>(eout + (size_t)s0 * DIM + d);
        v.x += a.x; v.y += a.y; v.z += a.z; v.w += a.w;
    }
    if (s1 >= 0) {
        float4 a = *reinterpret_cast<const float4*>(eout + (size_t)s1 * DIM + d);
        v.x += a.x; v.y += a.y; v.z += a.z; v.w += a.w;
    }
    *reinterpret_cast<float4*>(out + (size_t)t * DIM + d) = v;
}

// ---------------- host ----------------
extern "C" void kernel_launch(void* const* d_in, const int* in_sizes, int n_in,
                              void* d_out, int out_size)
{
    const float* x   = (const float*)d_in[0];
    const float* noi = (const float*)d_in[1];
    const float* Wr  = (const float*)d_in[2];
    const float* br  = (const float*)d_in[3];
    const float* Wn  = (const float*)d_in[4];
    const float* bn  = (const float*)d_in[5];
    const float* W1  = (const float*)d_in[6];
    const float* b1  = (const float*)d_in[7];
    const float* W2  = (const float*)d_in[8];
    const float* b2  = (const float*)d_in[9];
    const float* Ws1 = (const float*)d_in[10];
    const float* bs1 = (const float*)d_in[11];
    const float* Ws2 = (const float*)d_in[12];
    const float* bs2 = (const float*)d_in[13];
    float* out = (float*)d_out;

    __half *xf, *hsf, *hef, *w1t, *w2t, *ws1t, *ws2t;
    float *eout;
    int *tokE, *slotTok, *tokSlot; float *tokG, *slotGate;
    cudaGetSymbolAddress((void**)&xf, g_xf);
    cudaGetSymbolAddress((void**)&hsf, g_hsf);
    cudaGetSymbolAddress((void**)&hef, g_hef);
    cudaGetSymbolAddress((void**)&eout, g_eout);
    cudaGetSymbolAddress((void**)&w1t, g_w1t);
    cudaGetSymbolAddress((void**)&w2t, g_w2t);
    cudaGetSymbolAddress((void**)&ws1t, g_ws1t);
    cudaGetSymbolAddress((void**)&ws2t, g_ws2t);
    cudaGetSymbolAddress((void**)&tokE, g_tokE); cudaGetSymbolAddress((void**)&tokG, g_tokG);
    cudaGetSymbolAddress((void**)&slotTok, g_slotTok); cudaGetSymbolAddress((void**)&slotGate, g_slotGate);
    cudaGetSymbolAddress((void**)&tokSlot, g_tokSlot);

    cudaFuncSetAttribute(moe_gemm<1>, cudaFuncAttributeMaxDynamicSharedMemorySize, SMEM_BYTES);
    cudaFuncSetAttribute(moe_gemm<2>, cudaFuncAttributeMaxDynamicSharedMemorySize, SMEM_BYTES);

    const int writeLbl = (out_size > NTOK * DIM) ? 1 : 0;
    dim3 tb(32, 8);
    dim3 gW(32, 32, 2 * NE + 2);

    router_k<<<1024, 256>>>(x, noi, Wr, br, Wn, bn, tokE, tokG, xf, out, writeLbl); // 0
    prep_w_all_k<<<gW, tb>>>(W1, Ws1, W2, Ws2, w1t, ws1t, w2t, ws2t);               // 1
    scan_k<<<NE, 1024>>>(tokE, tokG, slotTok, slotGate, tokSlot, out, writeLbl);    // 2

    // 3: merged GEMM phase 1 (ncu-profiled launch)
    moe_gemm<1><<<NBLK_G, 256, SMEM_BYTES>>>(xf, xf, w1t, ws1t, b1, bs1,
                                             hef, hsf, nullptr, nullptr,
                                             slotTok, slotGate);

    // 4: merged GEMM phase 2 (no gap — weights already prepped)
    moe_gemm<2><<<NBLK_G, 256, SMEM_BYTES>>>(hef, hsf, w2t, ws2t, b2, bs2,
                                             nullptr, nullptr, eout, out,
                                             slotTok, slotGate);

    combine_k<<<NTOK, 256>>>(tokSlot, eout, out);                                   // 5
    (void)in_sizes; (void)n_in;
}